// round 15
// baseline (speedup 1.0000x reference)
#include <cuda_runtime.h>
#include <math.h>

#define FDIM 128
#define GMAX 50000
#define SEGB 32          // segments per MLP block
#define PAD  132         // sA row stride (floats): frag reads conflict-free

// ---------------- device scratch (zero-initialized .bss; self-restoring) ----------------
__device__ float  g_pool[(size_t)GMAX * FDIM];
__device__ float2 g_w1p[FDIM * FDIM];   // W1 pre-split into (tf32-hi, tf32-lo) pairs

__device__ __forceinline__ float tanh_fast(float x) {
    float r;
    asm("tanh.approx.f32 %0, %1;" : "=f"(r) : "f"(x));
    return r;
}

// tf32 split: hi = truncate-to-tf32(x) (exact), lo = x - hi, truncated to tf32.
__device__ __forceinline__ void tf32_split(float x, unsigned& hi, unsigned& lo) {
    unsigned bx = __float_as_uint(x);
    hi = bx & 0xFFFFE000u;
    float lof = x - __uint_as_float(hi);
    lo = __float_as_uint(lof) & 0xFFFFE000u;
}

__device__ __forceinline__ void mma_tf32(
    float& d0, float& d1, float& d2, float& d3,
    unsigned a0, unsigned a1, unsigned a2, unsigned a3,
    unsigned b0, unsigned b1)
{
    asm volatile(
        "mma.sync.aligned.m16n8k8.row.col.f32.tf32.tf32.f32 "
        "{%0,%1,%2,%3}, {%4,%5,%6,%7}, {%8,%9}, {%0,%1,%2,%3};"
        : "+f"(d0), "+f"(d1), "+f"(d2), "+f"(d3)
        : "r"(a0), "r"(a1), "r"(a2), "r"(a3), "r"(b0), "r"(b1));
}

// ---------------- kernel 1: stream h in node order, scatter-add into L2 pool ----------------
__global__ void __launch_bounds__(256) stream_pool_kernel(
    const float* __restrict__ h,
    const void*  __restrict__ seg,
    int N)
{
    __shared__ int s_is64;
    if (threadIdx.x == 0) {
        const unsigned int* w = (const unsigned int*)seg;
        unsigned int acc = 0;
        #pragma unroll
        for (int k = 0; k < 64; k++) acc |= w[2 * k + 1];
        s_is64 = (acc == 0u) ? 1 : 0;
    }
    __syncthreads();
    const int is64 = s_is64;

    const int warp = threadIdx.x >> 5;
    const int lane = threadIdx.x & 31;
    const int base = (blockIdx.x * 8 + warp) * 32;   // 32 consecutive nodes per warp
    if (base >= N) return;                           // uniform per warp
    const int cnt = min(32, N - base);

    int sid = 0;
    if (lane < cnt) {
        sid = is64 ? (int)((const long long*)seg)[base + lane]
                   : ((const int*)seg)[base + lane];
    }

    #pragma unroll 4
    for (int j = 0; j < 32; j++) {
        if (j >= cnt) break;
        const int s = __shfl_sync(0xffffffffu, sid, j);
        float4 v = __ldcs((const float4*)(h + (size_t)(base + j) * FDIM) + lane);
        float* dst = g_pool + (size_t)s * FDIM + lane * 4;
        asm volatile("red.global.add.v4.f32 [%0], {%1, %2, %3, %4};"
                     :: "l"(dst), "f"(v.x), "f"(v.y), "f"(v.z), "f"(v.w)
                     : "memory");
    }
}

// ---------------- kernel 1.5: pre-split W1 into (hi, lo) tf32 pairs ----------------
__global__ void __launch_bounds__(256) split_w1_kernel(const float* __restrict__ W1) {
    int i = blockIdx.x * 256 + threadIdx.x;     // 0..16383
    float v = __ldg(W1 + i);
    unsigned hi, lo;
    tf32_split(v, hi, lo);
    g_w1p[i] = make_float2(__uint_as_float(hi), __uint_as_float(lo));
}

// ---------------- kernel 2: tensor-core MLP head (pre-split B) ----------------
// 128 threads = 4 warps. Block: 32 segs x 128 cols. Warp w: seg stripe mrow=w&1,
// col half nhalf=w>>1 (64 cols = 8 n-tiles). 3-term tf32 compensation.
__global__ void __launch_bounds__(128) mlp_kernel(
    const float* __restrict__ b1,   // [128]
    const float* __restrict__ W2,   // [128]
    const float* __restrict__ b2,   // [1]
    float* __restrict__ y, int G)
{
    __shared__ float sA[SEGB][PAD];     // pooled tile (16.9 KB)
    __shared__ float sy[SEGB][2];

    const int tid  = threadIdx.x;
    const int warp = tid >> 5;
    const int lane = tid & 31;
    const int gid  = lane >> 2;         // group id 0..7
    const int tig  = lane & 3;          // thread in group 0..3
    const int mrow  = warp & 1;         // seg stripe (16 segs)
    const int nhalf = warp >> 1;        // column half (64 cols)
    const int gbase = blockIdx.x * SEGB;

    // ---- load pooled tile into smem; zero g_pool behind us ----
    const float4 z4 = make_float4(0.f, 0.f, 0.f, 0.f);
    #pragma unroll
    for (int it = 0; it < 8; it++) {
        int idx = it * 128 + tid;       // 0..1023 = 32 segs x 32 float4
        int s = idx >> 5;
        int c = idx & 31;
        int g = gbase + s;
        float4 v = z4;
        if (g < G) {
            float4* p = (float4*)(g_pool + (size_t)g * FDIM) + c;
            v = *p;
            *p = z4;                    // self-restore for the next replay
        }
        sA[s][4 * c + 0] = v.x;
        sA[s][4 * c + 1] = v.y;
        sA[s][4 * c + 2] = v.z;
        sA[s][4 * c + 3] = v.w;
    }
    __syncthreads();

    // ---- mma mainloop: 16 k-steps x 8 n-tiles ----
    float d[8][4];
    #pragma unroll
    for (int nt = 0; nt < 8; nt++)
        d[nt][0] = d[nt][1] = d[nt][2] = d[nt][3] = 0.f;

    const int sbase = mrow * 16;
    #pragma unroll 4
    for (int k0 = 0; k0 < FDIM; k0 += 8) {
        float fa0 = sA[sbase + gid][k0 + tig];
        float fa1 = sA[sbase + gid + 8][k0 + tig];
        float fa2 = sA[sbase + gid][k0 + tig + 4];
        float fa3 = sA[sbase + gid + 8][k0 + tig + 4];
        unsigned a0h, a0l, a1h, a1l, a2h, a2l, a3h, a3l;
        tf32_split(fa0, a0h, a0l);
        tf32_split(fa1, a1h, a1l);
        tf32_split(fa2, a2h, a2l);
        tf32_split(fa3, a3h, a3l);

        #pragma unroll
        for (int nt = 0; nt < 8; nt++) {
            const int n0 = nhalf * 64 + nt * 8;
            // pre-split B fragments: one LDG.64 each (hi, lo)
            float2 p0 = __ldg(&g_w1p[(k0 + tig) * FDIM + n0 + gid]);
            float2 p1 = __ldg(&g_w1p[(k0 + tig + 4) * FDIM + n0 + gid]);
            unsigned b0h = __float_as_uint(p0.x), b0l = __float_as_uint(p0.y);
            unsigned b1h = __float_as_uint(p1.x), b1l = __float_as_uint(p1.y);

            mma_tf32(d[nt][0], d[nt][1], d[nt][2], d[nt][3],
                     a0h, a1h, a2h, a3h, b0h, b1h);
            mma_tf32(d[nt][0], d[nt][1], d[nt][2], d[nt][3],
                     a0l, a1l, a2l, a3l, b0h, b1h);
            mma_tf32(d[nt][0], d[nt][1], d[nt][2], d[nt][3],
                     a0h, a1h, a2h, a3h, b0l, b1l);
        }
    }

    // ---- epilogue: bias, tanh, W2 dot, reduce over tig group (width 4) ----
    float p0 = 0.f, p1 = 0.f;          // rows gid, gid+8 of this stripe
    #pragma unroll
    for (int nt = 0; nt < 8; nt++) {
        const int c0 = nhalf * 64 + nt * 8 + 2 * tig;
        float bb0 = __ldg(b1 + c0),     bb1 = __ldg(b1 + c0 + 1);
        float w20 = __ldg(W2 + c0),     w21 = __ldg(W2 + c0 + 1);
        p0 = fmaf(tanh_fast(d[nt][0] + bb0), w20, p0);
        p0 = fmaf(tanh_fast(d[nt][1] + bb1), w21, p0);
        p1 = fmaf(tanh_fast(d[nt][2] + bb0), w20, p1);
        p1 = fmaf(tanh_fast(d[nt][3] + bb1), w21, p1);
    }
    p0 += __shfl_down_sync(0xffffffffu, p0, 2, 4);
    p0 += __shfl_down_sync(0xffffffffu, p0, 1, 4);
    p1 += __shfl_down_sync(0xffffffffu, p1, 2, 4);
    p1 += __shfl_down_sync(0xffffffffu, p1, 1, 4);
    if (tig == 0) {
        sy[sbase + gid][nhalf]     = p0;
        sy[sbase + gid + 8][nhalf] = p1;
    }
    __syncthreads();

    if (tid < SEGB) {
        int g = gbase + tid;
        if (g < G) y[g] = sy[tid][0] + sy[tid][1] + __ldg(b2);
    }
}

// ---------------- launch ----------------
extern "C" void kernel_launch(void* const* d_in, const int* in_sizes, int n_in,
                              void* d_out, int out_size) {
    const float* h   = (const float*)d_in[0];
    const void*  seg = d_in[1];
    const int N = in_sizes[0] / FDIM;
    const int G = out_size;          // OUT = 1

    int iw = -1;
    for (int i = 2; i < n_in; i++) {
        if (in_sizes[i] == FDIM * FDIM) { iw = i; break; }
    }
    const float* W1 = (const float*)d_in[iw];
    const float* b1 = (const float*)d_in[iw + 1];
    const float* W2 = (const float*)d_in[iw + 2];
    const float* b2 = (const float*)d_in[iw + 3];
    float* y = (float*)d_out;

    const int nodes_per_blk = 8 * 32;    // 8 warps x 32 nodes
    stream_pool_kernel<<<(N + nodes_per_blk - 1) / nodes_per_blk, 256>>>(h, seg, N);
    split_w1_kernel<<<FDIM * FDIM / 256, 256>>>(W1);
    mlp_kernel<<<(G + SEGB - 1) / SEGB, 128>>>(b1, W2, b2, y, G);
}

// round 16
// speedup vs baseline: 1.2520x; 1.2520x over previous
#include <cuda_runtime.h>
#include <math.h>

#define FDIM 128
#define GMAX 50000
#define CAP  192
#define OVF_MAX 4096

// ---------------- device scratch (zero-initialized .bss; self-restoring) ----------------
__device__ int g_cnt[GMAX];                 // per-segment node count (restored to 0 by pool)
__device__ int g_perm[(size_t)GMAX * CAP];  // bucketed node indices
__device__ int g_ovf[OVF_MAX];              // overflow node list (normally empty)
__device__ int g_novf;                      // overflow count (reset by pool's last block)
__device__ int g_is64;                      // seg dtype flag (written by scatter)
__device__ int g_done;                      // block-arrival ticket (reset by last block)

__device__ __forceinline__ float tanh_fast(float x) {
    float r;
    asm("tanh.approx.f32 %0, %1;" : "=f"(r) : "f"(x));
    return r;
}

__device__ __forceinline__ void facc(float4& a, const float4& v) {
    a.x += v.x; a.y += v.y; a.z += v.z; a.w += v.w;
}

// ---------------- kernel 1: scatter nodes into per-segment buckets (1 node/thread) ----------------
__global__ void __launch_bounds__(256) scatter_kernel(const void* __restrict__ seg, int N) {
    __shared__ int s_is64;
    if (threadIdx.x == 0) {
        // int64 ids < 2^32 have zero high words; 64 random int32 ids all-zero: p ~ 0
        const unsigned int* w = (const unsigned int*)seg;
        unsigned int acc = 0;
        #pragma unroll
        for (int k = 0; k < 64; k++) acc |= w[2 * k + 1];
        s_is64 = (acc == 0u) ? 1 : 0;
        if (blockIdx.x == 0) g_is64 = s_is64;
    }
    __syncthreads();

    const int i = blockIdx.x * blockDim.x + threadIdx.x;
    if (i >= N) return;
    const int s = s_is64 ? (int)((const long long*)seg)[i]
                         : ((const int*)seg)[i];
    int slot = atomicAdd(&g_cnt[s], 1);
    if (slot < CAP) {
        g_perm[(size_t)s * CAP + slot] = i;
    } else {
        int o = atomicAdd(&g_novf, 1);
        if (o < OVF_MAX) g_ovf[o] = i;
    }
}

// ---------------- kernel 2: fused gather-pool + per-warp MLP ----------------
// One segment per warp, fully independent warps (the structure that wins).
// Gather: 4 rows/iter with the NEXT int4 index prefetched (~8 rows in flight).
// Epilogue: per-warp GEMV from L1-hot W1, tanh.approx, warp-reduced dot.
__global__ void __launch_bounds__(256) pool_mlp_kernel(
    const float* __restrict__ h,
    const void*  __restrict__ seg,
    const float* __restrict__ W1,   // [128,128] row-major: W1[k][c]
    const float* __restrict__ b1,   // [128]
    const float* __restrict__ W2,   // [128]
    const float* __restrict__ b2,   // [1]
    float* __restrict__ y, int G)
{
    __shared__ float sp[8][FDIM];               // pooled row per warp (4 KB)
    const int warp = threadIdx.x >> 5;
    const int lane = threadIdx.x & 31;
    const int g = blockIdx.x * 8 + warp;
    const int nov = g_novf;                     // read before any block resets it

    if (g < G) {
        const int n = g_cnt[g];
        if (lane == 0) g_cnt[g] = 0;            // self-restore for next replay
        const int nn = min(n, CAP);
        const int* pm = &g_perm[(size_t)g * CAP];

        float4 a0 = make_float4(0.f, 0.f, 0.f, 0.f);
        float4 a1 = a0;

        // 4-row batches, index vector prefetched one iteration ahead
        int4 id = make_int4(0, 0, 0, 0);
        if (nn >= 4) id = __ldg((const int4*)pm);
        int i = 0;
        for (; i + 4 <= nn; i += 4) {
            int4 nx = id;
            if (i + 8 <= nn) nx = __ldg((const int4*)(pm + i + 4));
            float4 v0 = __ldcs((const float4*)(h + (size_t)id.x * FDIM) + lane);
            float4 v1 = __ldcs((const float4*)(h + (size_t)id.y * FDIM) + lane);
            float4 v2 = __ldcs((const float4*)(h + (size_t)id.z * FDIM) + lane);
            float4 v3 = __ldcs((const float4*)(h + (size_t)id.w * FDIM) + lane);
            facc(a0, v0); facc(a1, v1); facc(a0, v2); facc(a1, v3);
            id = nx;
        }
        for (; i < nn; i++) {
            int nd = __ldg(pm + i);
            float4 v = __ldcs((const float4*)(h + (size_t)nd * FDIM) + lane);
            facc(a0, v);
        }

        // overflow path (correctness safety net; empty for real data)
        if (nov > 0) {
            const int m = min(nov, OVF_MAX);
            const int is64 = g_is64;
            for (int k = 0; k < m; k++) {
                int nd = g_ovf[k];
                int s = is64 ? (int)((const long long*)seg)[nd]
                             : ((const int*)seg)[nd];
                if (s == g) {
                    float4 v = __ldcs((const float4*)(h + (size_t)nd * FDIM) + lane);
                    facc(a0, v);
                }
            }
        }

        float4 acc;
        acc.x = a0.x + a1.x; acc.y = a0.y + a1.y;
        acc.z = a0.z + a1.z; acc.w = a0.w + a1.w;
        ((float4*)sp[warp])[lane] = acc;
        __syncwarp();

        // hidden[4l..4l+3] = tanh(b1 + pooled @ W1); y = hidden . W2 + b2
        float4 bb = __ldg((const float4*)b1 + lane);
        float h0 = bb.x, h1 = bb.y, h2 = bb.z, h3 = bb.w;
        const float4* W1v = (const float4*)W1;  // row k, chunk lane
        const float* sA = sp[warp];

        #pragma unroll 4
        for (int k = 0; k < FDIM; k++) {
            float4 w = __ldg(W1v + k * 32 + lane);
            float pk = sA[k];
            h0 = fmaf(pk, w.x, h0);
            h1 = fmaf(pk, w.y, h1);
            h2 = fmaf(pk, w.z, h2);
            h3 = fmaf(pk, w.w, h3);
        }

        float4 w2 = __ldg((const float4*)W2 + lane);
        float p = tanh_fast(h0) * w2.x + tanh_fast(h1) * w2.y
                + tanh_fast(h2) * w2.z + tanh_fast(h3) * w2.w;

        #pragma unroll
        for (int off = 16; off; off >>= 1)
            p += __shfl_down_sync(0xffffffffu, p, off);
        if (lane == 0) y[g] = p + __ldg(b2);
    }

    // ---- elected last block resets overflow state for the next replay ----
    if (threadIdx.x == 0) {
        __threadfence();
        int t = atomicAdd(&g_done, 1);
        if (t == (int)gridDim.x - 1) {
            g_novf = 0;
            g_done = 0;
        }
    }
}

// ---------------- launch ----------------
extern "C" void kernel_launch(void* const* d_in, const int* in_sizes, int n_in,
                              void* d_out, int out_size) {
    const float* h   = (const float*)d_in[0];
    const void*  seg = d_in[1];
    const int N = in_sizes[0] / FDIM;
    const int G = out_size;          // OUT = 1

    int iw = -1;
    for (int i = 2; i < n_in; i++) {
        if (in_sizes[i] == FDIM * FDIM) { iw = i; break; }
    }
    const float* W1 = (const float*)d_in[iw];
    const float* b1 = (const float*)d_in[iw + 1];
    const float* W2 = (const float*)d_in[iw + 2];
    const float* b2 = (const float*)d_in[iw + 3];
    float* y = (float*)d_out;

    scatter_kernel<<<(N + 255) / 256, 256>>>(seg, N);
    pool_mlp_kernel<<<(G + 7) / 8, 256>>>(h, seg, W1, b1, W2, b2, y, G);
}